// round 5
// baseline (speedup 1.0000x reference)
#include <cuda_runtime.h>
#include <cstdint>
#include <cstddef>

#define NHEADS 12
#define HDIM   64
#define S_LEN  1024
#define BATCH  4
#define HID    768
#define BH     (BATCH * NHEADS)   // 48

// ---------------- scratch (__device__ globals; no allocation) ----------------
__device__ float g_Q[BH * S_LEN * HDIM];                 // 12.6 MB
__device__ float g_K[BH * S_LEN * HDIM];
__device__ float g_V[BH * S_LEN * HDIM];
__device__ float g_S[(size_t)BH * S_LEN * S_LEN];        // 201 MB scores/probs

// =============================================================================
// Kernel 1: fused QKV projection.  C[m][n] = sum_k X[m][k] * W[n][k] + bias[n]
// tile 128x128, K-tile 8, 256 threads, 8x8 microtile.
// Output written directly in [b, h, s, d] layout.
// =============================================================================
__global__ __launch_bounds__(256) void qkv_kernel(
    const float* __restrict__ X,
    const float* __restrict__ Wq, const float* __restrict__ bq,
    const float* __restrict__ Wk, const float* __restrict__ bk,
    const float* __restrict__ Wv, const float* __restrict__ bv)
{
    __shared__ float Xs[8 * 132];
    __shared__ float Ws[8 * 132];

    const float* W; const float* bias; float* out;
    int z = blockIdx.z;
    if (z == 0)      { W = Wq; bias = bq; out = g_Q; }
    else if (z == 1) { W = Wk; bias = bk; out = g_K; }
    else             { W = Wv; bias = bv; out = g_V; }

    int tid = threadIdx.x;
    int tx = tid & 15, ty = tid >> 4;
    int m0 = blockIdx.x * 128, n0 = blockIdx.y * 128;

    float acc[8][8];
    #pragma unroll
    for (int i = 0; i < 8; i++)
        #pragma unroll
        for (int j = 0; j < 8; j++) acc[i][j] = 0.f;

    int lrow = tid >> 1, lpart = tid & 1;

    for (int kt = 0; kt < HID; kt += 8) {
        float4 xv = *(const float4*)(X + (size_t)(m0 + lrow) * HID + kt + lpart * 4);
        float4 wv = *(const float4*)(W + (size_t)(n0 + lrow) * HID + kt + lpart * 4);
        __syncthreads();
        Xs[(lpart * 4 + 0) * 132 + lrow] = xv.x;
        Xs[(lpart * 4 + 1) * 132 + lrow] = xv.y;
        Xs[(lpart * 4 + 2) * 132 + lrow] = xv.z;
        Xs[(lpart * 4 + 3) * 132 + lrow] = xv.w;
        Ws[(lpart * 4 + 0) * 132 + lrow] = wv.x;
        Ws[(lpart * 4 + 1) * 132 + lrow] = wv.y;
        Ws[(lpart * 4 + 2) * 132 + lrow] = wv.z;
        Ws[(lpart * 4 + 3) * 132 + lrow] = wv.w;
        __syncthreads();
        #pragma unroll
        for (int kk = 0; kk < 8; kk++) {
            float a[8], b[8];
            #pragma unroll
            for (int i = 0; i < 8; i++) a[i] = Xs[kk * 132 + ty + 16 * i];
            #pragma unroll
            for (int j = 0; j < 8; j++) b[j] = Ws[kk * 132 + tx + 16 * j];
            #pragma unroll
            for (int i = 0; i < 8; i++)
                #pragma unroll
                for (int j = 0; j < 8; j++) acc[i][j] = fmaf(a[i], b[j], acc[i][j]);
        }
    }

    float bj[8];
    #pragma unroll
    for (int j = 0; j < 8; j++) bj[j] = bias[n0 + tx + 16 * j];

    #pragma unroll
    for (int i = 0; i < 8; i++) {
        int m = m0 + ty + 16 * i;
        int bb = m >> 10, s = m & 1023;
        #pragma unroll
        for (int j = 0; j < 8; j++) {
            int n = n0 + tx + 16 * j;
            int h = n >> 6, d = n & 63;
            out[(((size_t)(bb * NHEADS + h)) * S_LEN + s) * HDIM + d] = acc[i][j] + bj[j];
        }
    }
}

// =============================================================================
// Kernel 2: scores[l,r] = (q.k + q.D[t] + k.D[t]) / 8 + mask[b,r],
//           t = l - r + 1023.
// Per 64x64 (l,r) tile: load 128-row distance window Dw, compute
//   Cq = Q_tile @ Dw^T  and  Ck = K_tile @ Dw^T   (small GEMMs, in regs),
// stash them in smem, do the q.k GEMM, then gather the two bias diagonals.
// 256 threads, __launch_bounds__(256, 2): 2 CTAs/SM at 99.3 KB smem each.
// =============================================================================
__global__ __launch_bounds__(256, 2) void scores_kernel(
    const float* __restrict__ dist, const float* __restrict__ mask)
{
    extern __shared__ float sm[];
    float* Qs  = sm;            // 64 x 65  = 4160
    float* Ks  = sm + 4160;     // 64 x 65  = 4160
    float* Dw  = sm + 8320;     // 128 x 65 = 8320 (reused as CqS after phase B)
    float* CkS = sm + 16640;    // 64 x 128 = 8192
    float* CqS = Dw;            // 64 x 128 overlays Dw

    int tid = threadIdx.x;
    int tx = tid & 15, ty = tid >> 4;
    int bh = blockIdx.z, b = bh / NHEADS;
    int l0 = blockIdx.y << 6, r0 = blockIdx.x << 6;

    const float* Qp = g_Q + (size_t)bh * (S_LEN * HDIM);
    const float* Kp = g_K + (size_t)bh * (S_LEN * HDIM);

    for (int idx = tid; idx < 4096; idx += 256) {
        int l = idx >> 6, d = idx & 63;
        Qs[l * 65 + d] = Qp[(size_t)(l0 + l) * 64 + d];
        Ks[l * 65 + d] = Kp[(size_t)(r0 + l) * 64 + d];
    }
    int base = l0 - r0 + 960;   // window start: t = base + j, j in [0,127]
    for (int idx = tid; idx < 8192; idx += 256) {
        int j = idx >> 6, d = idx & 63;
        int t = base + j;
        Dw[j * 65 + d] = (t >= 0 && t < 2047) ? dist[(size_t)t * 64 + d] : 0.f;
    }
    __syncthreads();

    // Phase B: Cq[l][j] = sum_d Qs[l][d]*Dw[j][d];  Ck[r][j] likewise from Ks.
    float accq[4][8], acck[4][8];
    #pragma unroll
    for (int i = 0; i < 4; i++)
        #pragma unroll
        for (int j = 0; j < 8; j++) { accq[i][j] = 0.f; acck[i][j] = 0.f; }

    for (int d = 0; d < 64; d++) {
        float qa[4], ka[4], wb[8];
        #pragma unroll
        for (int i = 0; i < 4; i++) {
            qa[i] = Qs[(ty * 4 + i) * 65 + d];
            ka[i] = Ks[(ty * 4 + i) * 65 + d];
        }
        #pragma unroll
        for (int j = 0; j < 8; j++) wb[j] = Dw[(tx + (j << 4)) * 65 + d];
        #pragma unroll
        for (int i = 0; i < 4; i++)
            #pragma unroll
            for (int j = 0; j < 8; j++) {
                accq[i][j] = fmaf(qa[i], wb[j], accq[i][j]);
                acck[i][j] = fmaf(ka[i], wb[j], acck[i][j]);
            }
    }
    __syncthreads();   // everyone done reading Dw

    #pragma unroll
    for (int i = 0; i < 4; i++)
        #pragma unroll
        for (int j = 0; j < 8; j++) {
            CqS[(ty * 4 + i) * 128 + tx + (j << 4)] = accq[i][j];
            CkS[(ty * 4 + i) * 128 + tx + (j << 4)] = acck[i][j];
        }

    // Phase D: q.k 64x64 GEMM (reads only Qs/Ks; overlaps C-store latency)
    float acc[4][4];
    #pragma unroll
    for (int i = 0; i < 4; i++)
        #pragma unroll
        for (int r = 0; r < 4; r++) acc[i][r] = 0.f;

    for (int d = 0; d < 64; d++) {
        float qa[4], kb[4];
        #pragma unroll
        for (int i = 0; i < 4; i++) qa[i] = Qs[(ty * 4 + i) * 65 + d];
        #pragma unroll
        for (int r = 0; r < 4; r++) kb[r] = Ks[(tx + (r << 4)) * 65 + d];
        #pragma unroll
        for (int i = 0; i < 4; i++)
            #pragma unroll
            for (int r = 0; r < 4; r++) acc[i][r] = fmaf(qa[i], kb[r], acc[i][r]);
    }
    __syncthreads();   // CqS/CkS visible

    const float* mrow = mask + b * S_LEN + r0;
    #pragma unroll
    for (int i = 0; i < 4; i++) {
        int li = ty * 4 + i;
        float* outp = g_S + ((size_t)bh * S_LEN + (l0 + li)) * S_LEN + r0;
        #pragma unroll
        for (int r = 0; r < 4; r++) {
            int ri = tx + (r << 4);
            int j = li - ri + 63;                       // in [0,126]
            float sv = (acc[i][r] + CqS[li * 128 + j] + CkS[ri * 128 + j]) * 0.125f
                     + mrow[ri];
            outp[ri] = sv;
        }
    }
}

// =============================================================================
// Kernel 3: row softmax, in place.  Polynomial exp2 on the FMA pipe —
// avoids the ~340us MUFU.EX2 throughput wall (rt_SMSP=8).
// One warp per row, 4 rows per 128-thread block.
// =============================================================================
__device__ __forceinline__ float fast_exp(float x)
{
    float y = x * 1.4426950408889634f;       // x * log2(e)
    y = fmaxf(y, -120.f);
    float r = rintf(y);
    float f = y - r;                          // |f| <= 0.5
    float z = f * 0.6931471805599453f;        // |z| <= 0.3466
    float p = fmaf(z, 0.008333333f, 0.041666668f);
    p = fmaf(z, p, 0.16666667f);
    p = fmaf(z, p, 0.5f);
    p = fmaf(z, p, 1.0f);
    p = fmaf(z, p, 1.0f);
    int e = (int)r;
    float s = __int_as_float((e + 127) << 23);
    return s * p;
}

__global__ __launch_bounds__(128) void softmax_kernel()
{
    int warp = threadIdx.x >> 5, lane = threadIdx.x & 31;
    size_t row = (size_t)blockIdx.x * 4 + warp;
    float* p = g_S + row * S_LEN;

    float x[32];
    #pragma unroll
    for (int i = 0; i < 32; i++) x[i] = p[lane + (i << 5)];

    float m = x[0];
    #pragma unroll
    for (int i = 1; i < 32; i++) m = fmaxf(m, x[i]);
    #pragma unroll
    for (int o = 16; o; o >>= 1) m = fmaxf(m, __shfl_xor_sync(0xffffffffu, m, o));

    float sum = 0.f;
    #pragma unroll
    for (int i = 0; i < 32; i++) { x[i] = fast_exp(x[i] - m); sum += x[i]; }
    #pragma unroll
    for (int o = 16; o; o >>= 1) sum += __shfl_xor_sync(0xffffffffu, sum, o);

    float inv = 1.0f / sum;
    #pragma unroll
    for (int i = 0; i < 32; i++) p[lane + (i << 5)] = x[i] * inv;
}

// =============================================================================
// Kernel 4: ctx = P @ V, written straight to [B,S,H] output layout.
// tile 64 l x 64 d, K-tile 32, 256 threads, 4x4 microtile.
// =============================================================================
__global__ __launch_bounds__(256) void pv_kernel(float* __restrict__ out)
{
    __shared__ float Ps[64 * 33];
    __shared__ float Vs[32 * 64];

    int tid = threadIdx.x;
    int tx = tid & 15, ty = tid >> 4;
    int bh = blockIdx.y, l0 = blockIdx.x << 6;
    int b = bh / NHEADS, h = bh % NHEADS;

    const float* Pp = g_S + ((size_t)bh * S_LEN + l0) * S_LEN;
    const float* Vp = g_V + (size_t)bh * (S_LEN * HDIM);

    float acc[4][4];
    #pragma unroll
    for (int i = 0; i < 4; i++)
        #pragma unroll
        for (int j = 0; j < 4; j++) acc[i][j] = 0.f;

    for (int kt = 0; kt < S_LEN; kt += 32) {
        __syncthreads();
        for (int idx = tid; idx < 2048; idx += 256) {
            int l = idx >> 5, kk = idx & 31;
            Ps[l * 33 + kk] = Pp[(size_t)l * S_LEN + kt + kk];
        }
        for (int idx = tid; idx < 2048; idx += 256) {
            int kk = idx >> 6, d = idx & 63;
            Vs[kk * 64 + d] = Vp[(size_t)(kt + kk) * 64 + d];
        }
        __syncthreads();
        #pragma unroll
        for (int kk = 0; kk < 32; kk++) {
            float a[4], bb[4];
            #pragma unroll
            for (int i = 0; i < 4; i++) a[i] = Ps[(ty * 4 + i) * 33 + kk];
            #pragma unroll
            for (int j = 0; j < 4; j++) bb[j] = Vs[kk * 64 + tx + (j << 4)];
            #pragma unroll
            for (int i = 0; i < 4; i++)
                #pragma unroll
                for (int j = 0; j < 4; j++) acc[i][j] = fmaf(a[i], bb[j], acc[i][j]);
        }
    }

    #pragma unroll
    for (int i = 0; i < 4; i++)
        #pragma unroll
        for (int j = 0; j < 4; j++)
            out[((size_t)b * S_LEN + l0 + ty * 4 + i) * HID + h * HDIM + tx + (j << 4)]
                = acc[i][j];
}

// =============================================================================
extern "C" void kernel_launch(void* const* d_in, const int* in_sizes, int n_in,
                              void* d_out, int out_size)
{
    const float* hidden = (const float*)d_in[0];
    const float* mask   = (const float*)d_in[1];
    const float* Wq     = (const float*)d_in[2];
    const float* bq     = (const float*)d_in[3];
    const float* Wk     = (const float*)d_in[4];
    const float* bk     = (const float*)d_in[5];
    const float* Wv     = (const float*)d_in[6];
    const float* bv     = (const float*)d_in[7];
    const float* dist   = (const float*)d_in[8];
    float* out          = (float*)d_out;

    qkv_kernel<<<dim3(32, 6, 3), 256>>>(hidden, Wq, bq, Wk, bk, Wv, bv);

    static const int SCORES_SMEM = 24832 * 4;   // 99328 B
    cudaFuncSetAttribute(scores_kernel,
                         cudaFuncAttributeMaxDynamicSharedMemorySize, SCORES_SMEM);
    scores_kernel<<<dim3(16, 16, 48), 256, SCORES_SMEM>>>(dist, mask);

    softmax_kernel<<<(BH * S_LEN) / 4, 128>>>();

    pv_kernel<<<dim3(16, 48), 256>>>(out);
}